// round 7
// baseline (speedup 1.0000x reference)
#include <cuda_runtime.h>
#include <cuda_bf16.h>
#include <cstdint>
#include <cstddef>

// ---------------------------------------------------------------------------
// BiMiniGRU: B=8, L=8192, C=D=256
//   proj: 6x GEMM [65536,256]x[256,256] + bias (+sigmoid on z,s)
//         bf16x3 split on mma.sync (plain PTX, compute_103-legal)
//   One CTA = one 128-row M-tile; A loaded once, reused for all 6 weights.
//   Segment scan composition (pass1) fused into the GEMM epilogue.
//   scan: h[t] = (1-z)*h[t-1] + z*h~[t]  (fwd and reversed bwd)
//   out  = h_f * s_f + h_b * s_b
// ---------------------------------------------------------------------------

#define BSZ 8
#define LSZ 8192
#define DSZ 256
#define MSZ (BSZ * LSZ)          // 65536
#define LC  128                  // scan segment length == M-tile
#define NSEG (LSZ / LC)          // 64

// SMEM layout (bytes, from dynamic smem base)
//  A_HI: 4 k-chunks x [128 rows x 64 k] bf16, 128B rows SW128  = 65536
//  A_LO: same                                                   = 65536
//  B double buffer: 2 x (hi 16KB + lo 16KB)                     = 65536
#define SM_A_HI 0
#define SM_A_LO 65536
#define SM_B    131072
#define B_STG   32768            // per stage: hi at +0, lo at +16384
#define GEMM_SMEM 196608

#define SW128(o) ((o) ^ (((o) >> 3) & 0x70))

// ---------------------------------------------------------------------------
// Scratch (allocation-free rule: __device__ globals)
// widx order: 0=z_f, 1=h~_f, 2=s_f, 3=z_b, 4=h~_b, 5=s_b
// ---------------------------------------------------------------------------
__device__ float g_proj[6][(size_t)MSZ * DSZ];
__device__ __align__(16) __nv_bfloat16 g_wThi[6][DSZ * DSZ];
__device__ __align__(16) __nv_bfloat16 g_wTlo[6][DSZ * DSZ];
__device__ float g_segA[2 * BSZ * NSEG * DSZ];
__device__ float g_segB[2 * BSZ * NSEG * DSZ];
__device__ float g_carry[2 * BSZ * NSEG * DSZ];

// ---------------------------------------------------------------------------
// PTX helpers (plain PTX only)
// ---------------------------------------------------------------------------
__device__ __forceinline__ uint32_t smem_u32(const void* p) {
    uint32_t a;
    asm("{ .reg .u64 t; cvta.to.shared.u64 t, %1; cvt.u32.u64 %0, t; }"
        : "=r"(a) : "l"(p));
    return a;
}

#define CP16(dst, src) asm volatile( \
    "cp.async.cg.shared.global [%0], [%1], 16;" :: "r"(dst), "l"(src))
#define CP_COMMIT() asm volatile("cp.async.commit_group;" ::: "memory")
#define CP_WAIT0()  asm volatile("cp.async.wait_group 0;" ::: "memory")
#define CP_WAIT1()  asm volatile("cp.async.wait_group 1;" ::: "memory")

#define LDSM_X4(r, addr) asm volatile( \
    "ldmatrix.sync.aligned.m8n8.x4.shared.b16 {%0,%1,%2,%3}, [%4];" \
    : "=r"((r)[0]), "=r"((r)[1]), "=r"((r)[2]), "=r"((r)[3]) : "r"(addr))
#define LDSM_X2(r, addr) asm volatile( \
    "ldmatrix.sync.aligned.m8n8.x2.shared.b16 {%0,%1}, [%2];" \
    : "=r"((r)[0]), "=r"((r)[1]) : "r"(addr))

#define MMA_BF16(cc, a, b) asm volatile( \
    "mma.sync.aligned.m16n8k16.row.col.f32.bf16.bf16.f32 " \
    "{%0,%1,%2,%3}, {%4,%5,%6,%7}, {%8,%9}, {%0,%1,%2,%3};" \
    : "+f"((cc)[0]), "+f"((cc)[1]), "+f"((cc)[2]), "+f"((cc)[3]) \
    : "r"((a)[0]), "r"((a)[1]), "r"((a)[2]), "r"((a)[3]), \
      "r"((b)[0]), "r"((b)[1]))

__device__ __forceinline__ void split2(float v, __nv_bfloat16& h, __nv_bfloat16& l) {
    h = __float2bfloat16(v);
    l = __float2bfloat16(v - __bfloat162float(h));
}
__device__ __forceinline__ uint32_t pack2(__nv_bfloat16 a, __nv_bfloat16 b) {
    __nv_bfloat162 t; t.x = a; t.y = b;
    return *reinterpret_cast<uint32_t*>(&t);
}

// ---------------------------------------------------------------------------
// Precompute: W^T (n-major rows of k) bf16 hi/lo per weight
// ---------------------------------------------------------------------------
struct WPtrs { const float* W[6]; };
__global__ void prep_w(WPtrs wp) {
    int widx = blockIdx.x;
    int n = blockIdx.y;
    int k = threadIdx.x;
    float v = wp.W[widx][(size_t)k * DSZ + n];
    __nv_bfloat16 h, l;
    split2(v, h, l);
    g_wThi[widx][n * DSZ + k] = h;
    g_wTlo[widx][n * DSZ + k] = l;
}

// ---------------------------------------------------------------------------
// Fused projection kernel. grid(512) = M-tiles, 256 threads (8 warps 2m x 4n,
// warp tile 64x32). Loops 6 weights x 2 n-halves; A resident in SMEM.
// Epilogue: bias+activation stores; then fused scan pass1 for this segment.
// ---------------------------------------------------------------------------
struct BiasPtrs { const float* b[6]; };

__global__ __launch_bounds__(256, 1)
void gemm_fused(BiasPtrs gb, const float* __restrict__ xs) {
    extern __shared__ __align__(128) char sm[];
    uint32_t sbase = smem_u32(sm);

    const int m0   = blockIdx.x * 128;
    const int t    = threadIdx.x;
    const int lane = t & 31;
    const int wid  = t >> 5;
    const int wm   = (wid & 1) * 64;
    const int wn   = (wid >> 1) * 32;

    // ---- B chunk loader: q = ((w*2)+nh)*4 + kc, buffer = q & 1 ----
    auto loadB = [&](int q) {
        const int w  = q >> 3;
        const int nh = (q >> 2) & 1;
        const int kc = q & 3;
        const __nv_bfloat16* __restrict__ Bh = g_wThi[w];
        const __nv_bfloat16* __restrict__ Bl = g_wTlo[w];
        uint32_t so = sbase + SM_B + (q & 1) * B_STG;
        // 128 rows x 8 16B-units = 1024 units; 256 threads -> 4 each (hi & lo)
        #pragma unroll
        for (int it = 0; it < 4; it++) {
            int seg = t + it * 256;
            int row = seg >> 3;              // 0..127 (n within half)
            int u   = seg & 7;               // 16B unit in 128B row
            uint32_t sw = SW128((uint32_t)(row * 128 + u * 16));
            size_t gsrc = (size_t)(nh * 128 + row) * DSZ + kc * 64 + u * 8;
            CP16(so + sw, Bh + gsrc);
            CP16(so + 16384 + sw, Bl + gsrc);
        }
    };

    // ---- prefetch first B chunk, then load+split the FULL A tile ----
    loadB(0);
    CP_COMMIT();
    {
        const float4* X4 = reinterpret_cast<const float4*>(xs);
        // 128 rows x 64 float4 = 8192 items; 256 threads x 32 iters
        #pragma unroll
        for (int it = 0; it < 32; it++) {
            int g   = t + it * 256;          // 0..8191
            int row = g >> 6;                // 0..127
            int f4  = g & 63;                // float4 index within 256-float row
            float4 v = X4[(size_t)(m0 + row) * 64 + f4];
            __nv_bfloat16 h0, h1, h2, h3, l0, l1, l2, l3;
            split2(v.x, h0, l0); split2(v.y, h1, l1);
            split2(v.z, h2, l2); split2(v.w, h3, l3);
            uint2 uh, ul;
            uh.x = pack2(h0, h1); uh.y = pack2(h2, h3);
            ul.x = pack2(l0, l1); ul.y = pack2(l2, l3);
            int chunk = f4 >> 4;             // k-chunk (16 float4 per 64-k chunk)
            uint32_t sw = SW128((uint32_t)(row * 128 + (f4 & 15) * 8));
            *reinterpret_cast<uint2*>(sm + SM_A_HI + chunk * 16384 + sw) = uh;
            *reinterpret_cast<uint2*>(sm + SM_A_LO + chunk * 16384 + sw) = ul;
        }
    }

    const int g = lane >> 3, r = lane & 7;

    // ---- main loop: 6 weights x 2 n-halves x 4 k-chunks ----
    int q = 0;
    for (int w = 0; w < 6; w++) {
        const bool do_sig = (w % 3) != 1;    // z, s sigmoid; h~ raw
        const float* __restrict__ bias = gb.b[w];
        float* __restrict__ Out = g_proj[w];
        for (int nh = 0; nh < 2; nh++) {
            float c[4][4][4];
            #pragma unroll
            for (int mi = 0; mi < 4; mi++)
                #pragma unroll
                for (int ni = 0; ni < 4; ni++)
                    #pragma unroll
                    for (int p = 0; p < 4; p++) c[mi][ni][p] = 0.0f;

            for (int kc = 0; kc < 4; kc++, q++) {
                if (q < 47) { loadB(q + 1); CP_COMMIT(); CP_WAIT1(); }
                else        { CP_WAIT0(); }
                __syncthreads();

                uint32_t sa = sbase + kc * 16384;
                uint32_t sb = sbase + SM_B + (q & 1) * B_STG;
                #pragma unroll
                for (int ks = 0; ks < 4; ks++) {
                    uint32_t aoff = SW128((uint32_t)(
                        (wm + (g & 1) * 8 + r) * 128 + (ks * 16 + (g >> 1) * 8) * 2));
                    uint32_t boff = SW128((uint32_t)(
                        (wn + r) * 128 + (ks * 16 + (g & 1) * 8) * 2));
                    uint32_t ah[4][4], al[4][4], bh[4][2], bl[4][2];
                    #pragma unroll
                    for (int mi = 0; mi < 4; mi++) {
                        LDSM_X4(ah[mi], sa + SM_A_HI + aoff + mi * 2048);
                        LDSM_X4(al[mi], sa + SM_A_LO + aoff + mi * 2048);
                    }
                    #pragma unroll
                    for (int ni = 0; ni < 4; ni++) {
                        LDSM_X2(bh[ni], sb + boff + ni * 1024);
                        LDSM_X2(bl[ni], sb + 16384 + boff + ni * 1024);
                    }
                    #pragma unroll
                    for (int mi = 0; mi < 4; mi++)
                        #pragma unroll
                        for (int ni = 0; ni < 4; ni++) {
                            MMA_BF16(c[mi][ni], ah[mi], bh[ni]);   // hi*hi
                            MMA_BF16(c[mi][ni], ah[mi], bl[ni]);   // hi*lo
                            MMA_BF16(c[mi][ni], al[mi], bh[ni]);   // lo*hi
                        }
                }
                __syncthreads();
            }

            // ---- epilogue for this (w, nh) ----
            #pragma unroll
            for (int ni = 0; ni < 4; ni++) {
                const int col = nh * 128 + wn + ni * 8 + (lane & 3) * 2;
                const float2 bb = *reinterpret_cast<const float2*>(bias + col);
                #pragma unroll
                for (int mi = 0; mi < 4; mi++) {
                    const int row = m0 + wm + mi * 16 + (lane >> 2);
                    float v0 = c[mi][ni][0] + bb.x;
                    float v1 = c[mi][ni][1] + bb.y;
                    float v2 = c[mi][ni][2] + bb.x;
                    float v3 = c[mi][ni][3] + bb.y;
                    if (do_sig) {
                        v0 = 1.0f / (1.0f + __expf(-v0));
                        v1 = 1.0f / (1.0f + __expf(-v1));
                        v2 = 1.0f / (1.0f + __expf(-v2));
                        v3 = 1.0f / (1.0f + __expf(-v3));
                    }
                    float2 p0; p0.x = v0; p0.y = v1;
                    float2 p1; p1.x = v2; p1.y = v3;
                    *reinterpret_cast<float2*>(Out + (size_t)row * DSZ + col) = p0;
                    *reinterpret_cast<float2*>(Out + (size_t)(row + 8) * DSZ + col) = p1;
                }
            }
        }
    }

    // ---- fused scan pass1: compose this segment's affine map, both dirs ----
    __syncthreads();   // all projections for this tile visible block-wide
    const int d   = t;
    const int b   = m0 >> 13;                 // batch
    const int seg = (m0 & (LSZ - 1)) >> 7;    // fwd segment index
    const float* __restrict__ Zf = g_proj[0];
    const float* __restrict__ Hf = g_proj[1];
    const float* __restrict__ Zb = g_proj[3];
    const float* __restrict__ Hb = g_proj[4];

    float A1 = 1.0f, B1 = 0.0f;   // forward (ascending rows)
    float A2 = 1.0f, B2 = 0.0f;   // backward (descending rows)
    #pragma unroll 4
    for (int i = 0; i < LC; i++) {
        size_t fi = (size_t)(m0 + i) * DSZ + d;
        size_t bi = (size_t)(m0 + LC - 1 - i) * DSZ + d;
        float z1 = Zf[fi], h1 = Hf[fi];
        float a1 = 1.0f - z1;
        A1 = A1 * a1;
        B1 = fmaf(a1, B1, z1 * h1);
        float z2 = Zb[bi], h2 = Hb[bi];
        float a2 = 1.0f - z2;
        A2 = A2 * a2;
        B2 = fmaf(a2, B2, z2 * h2);
    }
    size_t of = (((size_t)0 * BSZ + b) * NSEG + seg) * DSZ + d;
    size_t ob = (((size_t)BSZ + b) * NSEG + (NSEG - 1 - seg)) * DSZ + d;
    g_segA[of] = A1;  g_segB[of] = B1;
    g_segA[ob] = A2;  g_segB[ob] = B2;
}

// ---------------------------------------------------------------------------
// Scan pass 2: sequential combine over NSEG segments; register-batched.
// grid (BSZ, 2), block DSZ
// ---------------------------------------------------------------------------
__global__ void scan_pass2(const float* __restrict__ h0f,
                           const float* __restrict__ h0b) {
    const int d   = threadIdx.x;
    const int b   = blockIdx.x;
    const int dir = blockIdx.y;
    float h = dir ? h0b[d] : h0f[d];
    size_t base = (((size_t)dir * BSZ + b) * NSEG) * DSZ + d;
    for (int sc = 0; sc < NSEG / 16; sc++) {
        float rA[16], rB[16];
        #pragma unroll
        for (int s = 0; s < 16; s++) {
            size_t o = base + (size_t)(sc * 16 + s) * DSZ;
            rA[s] = g_segA[o];
            rB[s] = g_segB[o];
        }
        #pragma unroll
        for (int s = 0; s < 16; s++) {
            size_t o = base + (size_t)(sc * 16 + s) * DSZ;
            g_carry[o] = h;
            h = fmaf(rA[s], h, rB[s]);
        }
    }
}

// ---------------------------------------------------------------------------
// Scan out: both directions fused; fwd contribution staged in SMEM (128KB).
// grid (NSEG, BSZ), block DSZ
// ---------------------------------------------------------------------------
__global__ void scan_out(float* __restrict__ out) {
    extern __shared__ float sv[];
    const int d   = threadIdx.x;
    const int seg = blockIdx.x;
    const int b   = blockIdx.y;
    const float* __restrict__ Zf = g_proj[0];
    const float* __restrict__ Hf = g_proj[1];
    const float* __restrict__ Sf = g_proj[2];
    const float* __restrict__ Zb = g_proj[3];
    const float* __restrict__ Hb = g_proj[4];
    const float* __restrict__ Sb = g_proj[5];

    size_t rowbase = ((size_t)b * LSZ + (size_t)seg * LC) * DSZ + d;

    // forward
    float h = g_carry[(((size_t)0 * BSZ + b) * NSEG + seg) * DSZ + d];
    #pragma unroll 4
    for (int i = 0; i < LC; i++) {
        size_t idx = rowbase + (size_t)i * DSZ;
        float z = Zf[idx];
        h = fmaf(1.0f - z, h, z * Hf[idx]);
        sv[i * DSZ + d] = h * Sf[idx];
    }
    // backward (bwd segment NSEG-1-seg covers these rows, reversed)
    const int sb = NSEG - 1 - seg;
    float hb = g_carry[(((size_t)BSZ + b) * NSEG + sb) * DSZ + d];
    #pragma unroll 4
    for (int j = 0; j < LC; j++) {
        int i = LC - 1 - j;
        size_t idx = rowbase + (size_t)i * DSZ;
        float z = Zb[idx];
        hb = fmaf(1.0f - z, hb, z * Hb[idx]);
        out[idx] = sv[i * DSZ + d] + hb * Sb[idx];
    }
}

// ---------------------------------------------------------------------------
// Launch. Inputs: 0 xs, 1 Wh1, 2 bh1, 3 Wz1, 4 bz1, 5 Ws1, 6 bs1, 7 h01,
//   8 Wh_1, 9 bh_1, 10 Wz_1, 11 bz_1, 12 Ws_1, 13 bs_1, 14 h0_1
// ---------------------------------------------------------------------------
extern "C" void kernel_launch(void* const* d_in, const int* in_sizes, int n_in,
                              void* d_out, int out_size) {
    cudaFuncSetAttribute(gemm_fused,
                         cudaFuncAttributeMaxDynamicSharedMemorySize, GEMM_SMEM);
    cudaFuncSetAttribute(scan_out,
                         cudaFuncAttributeMaxDynamicSharedMemorySize, LC * DSZ * 4);

    // widx: 0=z_f(Wz1), 1=h_f(Wh1), 2=s_f(Ws1), 3=z_b(Wz_1), 4=h_b(Wh_1), 5=s_b(Ws_1)
    WPtrs wp;
    wp.W[0] = (const float*)d_in[3];
    wp.W[1] = (const float*)d_in[1];
    wp.W[2] = (const float*)d_in[5];
    wp.W[3] = (const float*)d_in[10];
    wp.W[4] = (const float*)d_in[8];
    wp.W[5] = (const float*)d_in[12];
    BiasPtrs bp;
    bp.b[0] = (const float*)d_in[4];
    bp.b[1] = (const float*)d_in[2];
    bp.b[2] = (const float*)d_in[6];
    bp.b[3] = (const float*)d_in[11];
    bp.b[4] = (const float*)d_in[9];
    bp.b[5] = (const float*)d_in[13];

    prep_w<<<dim3(6, 256), 256>>>(wp);
    gemm_fused<<<MSZ / 128, 256, GEMM_SMEM>>>(bp, (const float*)d_in[0]);
    scan_pass2<<<dim3(BSZ, 2), DSZ>>>((const float*)d_in[7], (const float*)d_in[14]);
    scan_out<<<dim3(NSEG, BSZ), DSZ, LC * DSZ * 4>>>((float*)d_out);
}

// round 8
// speedup vs baseline: 2.3201x; 2.3201x over previous
#include <cuda_runtime.h>
#include <cuda_fp16.h>
#include <cstdint>
#include <cstddef>

// ---------------------------------------------------------------------------
// BiMiniGRU: B=8, L=8192, C=D=256
//   proj: 6x GEMM [65536,256]x[256,256] + bias (+sigmoid on z,s)
//         fp16 mma.sync (f32 accum), plain PTX (compute_103-legal)
//   One CTA = (128-row M-tile, direction); A resident fp16 in SMEM (64KB).
//   Fused per-direction scan pass1 at 64-step half segments.
//   scan: h[t] = (1-z)*h[t-1] + z*h~[t]; out = h_f*s_f + h_b*s_b
// ---------------------------------------------------------------------------

#define BSZ 8
#define LSZ 8192
#define DSZ 256
#define MSZ (BSZ * LSZ)          // 65536
#define SEGL 64                  // scan segment length
#define NSEG2 128                // segments per direction (LSZ/SEGL)

// SMEM: A 4 chunks x 16KB (128 rows x 64 k fp16, SW128) + B 3 stages x 16KB
#define SM_A 0
#define SM_B 65536
#define GEMM_SMEM (65536 + 3 * 16384)    // 114688 -> 2 CTAs/SM

#define SW128(o) ((o) ^ (((o) >> 3) & 0x70))

// ---------------------------------------------------------------------------
// Scratch (__device__ globals; allocation-free rule)
// widx order: 0=z_f, 1=h~_f, 2=s_f, 3=z_b, 4=h~_b, 5=s_b   (fp16 storage)
// ---------------------------------------------------------------------------
__device__ __align__(16) __half g_proj[6][(size_t)MSZ * DSZ];
__device__ __align__(16) __half g_wT[6][DSZ * DSZ];
__device__ float g_segA[2 * BSZ * NSEG2 * DSZ];
__device__ float g_segB[2 * BSZ * NSEG2 * DSZ];
__device__ float g_carry[2 * BSZ * NSEG2 * DSZ];

// ---------------------------------------------------------------------------
// PTX helpers (plain PTX only)
// ---------------------------------------------------------------------------
__device__ __forceinline__ uint32_t smem_u32(const void* p) {
    uint32_t a;
    asm("{ .reg .u64 t; cvta.to.shared.u64 t, %1; cvt.u32.u64 %0, t; }"
        : "=r"(a) : "l"(p));
    return a;
}

#define CP16(dst, src) asm volatile( \
    "cp.async.cg.shared.global [%0], [%1], 16;" :: "r"(dst), "l"(src))
#define CP_COMMIT() asm volatile("cp.async.commit_group;" ::: "memory")
#define CP_WAIT1()  asm volatile("cp.async.wait_group 1;" ::: "memory")

#define LDSM_X4(r, addr) asm volatile( \
    "ldmatrix.sync.aligned.m8n8.x4.shared.b16 {%0,%1,%2,%3}, [%4];" \
    : "=r"((r)[0]), "=r"((r)[1]), "=r"((r)[2]), "=r"((r)[3]) : "r"(addr))
#define LDSM_X2(r, addr) asm volatile( \
    "ldmatrix.sync.aligned.m8n8.x2.shared.b16 {%0,%1}, [%2];" \
    : "=r"((r)[0]), "=r"((r)[1]) : "r"(addr))

#define MMA_F16(cc, a, b) asm volatile( \
    "mma.sync.aligned.m16n8k16.row.col.f32.f16.f16.f32 " \
    "{%0,%1,%2,%3}, {%4,%5,%6,%7}, {%8,%9}, {%0,%1,%2,%3};" \
    : "+f"((cc)[0]), "+f"((cc)[1]), "+f"((cc)[2]), "+f"((cc)[3]) \
    : "r"((a)[0]), "r"((a)[1]), "r"((a)[2]), "r"((a)[3]), \
      "r"((b)[0]), "r"((b)[1]))

// ---------------------------------------------------------------------------
// Precompute: W^T (n-major rows of k) fp16 per weight
// ---------------------------------------------------------------------------
struct WPtrs { const float* W[6]; };
__global__ void prep_w(WPtrs wp) {
    int widx = blockIdx.x;
    int n = blockIdx.y;
    int k = threadIdx.x;
    g_wT[widx][n * DSZ + k] = __float2half_rn(wp.W[widx][(size_t)k * DSZ + n]);
}

// ---------------------------------------------------------------------------
// Fused projection kernel. grid (512 tiles, 2 dirs), 256 threads
// (8 warps 2m x 4n; warp tile 64x32). A resident; 3 weights x 2 nh x 4 kc.
// Epilogue: bias+activation fp16 stores; then fused pass1 (two 64-halves).
// ---------------------------------------------------------------------------
struct BiasPtrs { const float* b[6]; };

__global__ __launch_bounds__(256, 2)
void gemm_fused(BiasPtrs gb, const float* __restrict__ xs) {
    extern __shared__ __align__(128) char sm[];
    uint32_t sbase = smem_u32(sm);

    const int m0   = blockIdx.x * 128;
    const int dir  = blockIdx.y;
    const int t    = threadIdx.x;
    const int lane = t & 31;
    const int wid  = t >> 5;
    const int wm   = (wid & 1) * 64;
    const int wn   = (wid >> 1) * 32;

    // ---- B chunk loader: q = (wl*2 + nh)*4 + kc, stage = q % 3 ----
    auto loadB = [&](int q) {
        const int wl = q >> 3;
        const int nh = (q >> 2) & 1;
        const int kc = q & 3;
        const __half* __restrict__ Bp = g_wT[dir * 3 + wl];
        uint32_t so = sbase + SM_B + (q % 3) * 16384;
        #pragma unroll
        for (int it = 0; it < 4; it++) {
            int seg = t + it * 256;
            int row = seg >> 3;              // 0..127 (n within half)
            int u   = seg & 7;               // 16B unit in 128B row
            uint32_t sw = SW128((uint32_t)(row * 128 + u * 16));
            CP16(so + sw, Bp + (size_t)(nh * 128 + row) * DSZ + kc * 64 + u * 8);
        }
    };

    loadB(0); CP_COMMIT();
    loadB(1); CP_COMMIT();

    // ---- load + convert the full A tile (128 rows x 256 k fp16) ----
    {
        const float4* X4 = reinterpret_cast<const float4*>(xs);
        #pragma unroll
        for (int it = 0; it < 32; it++) {
            int g   = t + it * 256;          // 0..8191
            int row = g >> 6;                // 0..127
            int f4  = g & 63;                // float4 within 256-float row
            float4 v = X4[(size_t)(m0 + row) * 64 + f4];
            __half2 p01 = __floats2half2_rn(v.x, v.y);
            __half2 p23 = __floats2half2_rn(v.z, v.w);
            uint2 u2;
            u2.x = *reinterpret_cast<uint32_t*>(&p01);
            u2.y = *reinterpret_cast<uint32_t*>(&p23);
            int chunk = f4 >> 4;             // k-chunk of 64
            uint32_t sw = SW128((uint32_t)(row * 128 + (f4 & 15) * 8));
            *reinterpret_cast<uint2*>(sm + SM_A + chunk * 16384 + sw) = u2;
        }
    }

    const int gg = lane >> 3, r = lane & 7;

    // ---- main loop: 3 weights x 2 n-halves x 4 k-chunks (24 iters) ----
    int q = 0;
    for (int wl = 0; wl < 3; wl++) {
        const bool do_sig = (wl != 1);       // z, s sigmoid; h~ raw
        const float* __restrict__ bias = gb.b[dir * 3 + wl];
        __half* __restrict__ Out = g_proj[dir * 3 + wl];
        for (int nh = 0; nh < 2; nh++) {
            float c[4][4][4];
            #pragma unroll
            for (int mi = 0; mi < 4; mi++)
                #pragma unroll
                for (int ni = 0; ni < 4; ni++)
                    #pragma unroll
                    for (int p = 0; p < 4; p++) c[mi][ni][p] = 0.0f;

            for (int kc = 0; kc < 4; kc++, q++) {
                CP_WAIT1();                  // group q complete
                __syncthreads();             // visibility + prev compute done
                if (q + 2 < 24) loadB(q + 2);
                CP_COMMIT();

                uint32_t sa = sbase + SM_A + kc * 16384;
                uint32_t sb = sbase + SM_B + (q % 3) * 16384;
                #pragma unroll
                for (int ks = 0; ks < 4; ks++) {
                    uint32_t aoff = SW128((uint32_t)(
                        (wm + (gg & 1) * 8 + r) * 128 + (ks * 16 + (gg >> 1) * 8) * 2));
                    uint32_t boff = SW128((uint32_t)(
                        (wn + r) * 128 + (ks * 16 + (gg & 1) * 8) * 2));
                    uint32_t af[4][4], bf[4][2];
                    #pragma unroll
                    for (int mi = 0; mi < 4; mi++)
                        LDSM_X4(af[mi], sa + aoff + mi * 2048);
                    #pragma unroll
                    for (int ni = 0; ni < 4; ni++)
                        LDSM_X2(bf[ni], sb + boff + ni * 1024);
                    #pragma unroll
                    for (int mi = 0; mi < 4; mi++)
                        #pragma unroll
                        for (int ni = 0; ni < 4; ni++)
                            MMA_F16(c[mi][ni], af[mi], bf[ni]);
                }
            }

            // ---- epilogue for this (wl, nh): bias, act, fp16 store ----
            #pragma unroll
            for (int ni = 0; ni < 4; ni++) {
                const int col = nh * 128 + wn + ni * 8 + (lane & 3) * 2;
                const float2 bb = *reinterpret_cast<const float2*>(bias + col);
                #pragma unroll
                for (int mi = 0; mi < 4; mi++) {
                    const int row = m0 + wm + mi * 16 + (lane >> 2);
                    float v0 = c[mi][ni][0] + bb.x;
                    float v1 = c[mi][ni][1] + bb.y;
                    float v2 = c[mi][ni][2] + bb.x;
                    float v3 = c[mi][ni][3] + bb.y;
                    if (do_sig) {
                        v0 = 1.0f / (1.0f + __expf(-v0));
                        v1 = 1.0f / (1.0f + __expf(-v1));
                        v2 = 1.0f / (1.0f + __expf(-v2));
                        v3 = 1.0f / (1.0f + __expf(-v3));
                    }
                    *reinterpret_cast<__half2*>(Out + (size_t)row * DSZ + col)
                        = __floats2half2_rn(v0, v1);
                    *reinterpret_cast<__half2*>(Out + (size_t)(row + 8) * DSZ + col)
                        = __floats2half2_rn(v2, v3);
                }
            }
        }
    }

    // ---- fused pass1: two 64-step half-segment affine maps, this dir ----
    __syncthreads();   // all global stores of this CTA visible block-wide
    const int d  = t;
    const int b  = m0 >> 13;                  // batch
    const int s6 = (m0 & (LSZ - 1)) >> 6;     // first 64-seg index (even)
    const __half* __restrict__ Z = g_proj[dir * 3 + 0];
    const __half* __restrict__ H = g_proj[dir * 3 + 1];

    if (dir == 0) {
        #pragma unroll
        for (int part = 0; part < 2; part++) {
            float A = 1.0f, Bc = 0.0f;
            #pragma unroll 4
            for (int i = 0; i < SEGL; i++) {
                size_t idx = (size_t)(m0 + part * SEGL + i) * DSZ + d;
                float z  = __half2float(Z[idx]);
                float ht = __half2float(H[idx]);
                float a = 1.0f - z;
                A = A * a;
                Bc = fmaf(a, Bc, z * ht);
            }
            size_t o = (((size_t)b) * NSEG2 + (s6 + part)) * DSZ + d;
            g_segA[o] = A;  g_segB[o] = Bc;
        }
    } else {
        // bwd: rows [m0+64,m0+128) desc -> seg 126-s6; [m0,m0+64) desc -> 127-s6
        #pragma unroll
        for (int part = 0; part < 2; part++) {
            float A = 1.0f, Bc = 0.0f;
            #pragma unroll 4
            for (int i = 0; i < SEGL; i++) {
                size_t idx = (size_t)(m0 + (1 - part) * SEGL + (SEGL - 1 - i)) * DSZ + d;
                float z  = __half2float(Z[idx]);
                float ht = __half2float(H[idx]);
                float a = 1.0f - z;
                A = A * a;
                Bc = fmaf(a, Bc, z * ht);
            }
            size_t o = (((size_t)BSZ + b) * NSEG2 + (126 - s6 + part)) * DSZ + d;
            g_segA[o] = A;  g_segB[o] = Bc;
        }
    }
}

// ---------------------------------------------------------------------------
// Scan pass 2: sequential combine over 128 segments; register-batched.
// grid (BSZ, 2), block DSZ
// ---------------------------------------------------------------------------
__global__ void scan_pass2(const float* __restrict__ h0f,
                           const float* __restrict__ h0b) {
    const int d   = threadIdx.x;
    const int b   = blockIdx.x;
    const int dir = blockIdx.y;
    float h = dir ? h0b[d] : h0f[d];
    size_t base = (((size_t)dir * BSZ + b) * NSEG2) * DSZ + d;
    for (int sc = 0; sc < NSEG2 / 16; sc++) {
        float rA[16], rB[16];
        #pragma unroll
        for (int s = 0; s < 16; s++) {
            size_t o = base + (size_t)(sc * 16 + s) * DSZ;
            rA[s] = g_segA[o];
            rB[s] = g_segB[o];
        }
        #pragma unroll
        for (int s = 0; s < 16; s++) {
            size_t o = base + (size_t)(sc * 16 + s) * DSZ;
            g_carry[o] = h;
            h = fmaf(rA[s], h, rB[s]);
        }
    }
}

// ---------------------------------------------------------------------------
// Scan out: both directions fused; fwd staged in 64KB SMEM (3 CTAs/SM).
// grid (NSEG2, BSZ), block DSZ
// ---------------------------------------------------------------------------
__global__ void scan_out(float* __restrict__ out) {
    extern __shared__ float sv[];
    const int d   = threadIdx.x;
    const int seg = blockIdx.x;
    const int b   = blockIdx.y;
    const __half* __restrict__ Zf = g_proj[0];
    const __half* __restrict__ Hf = g_proj[1];
    const __half* __restrict__ Sf = g_proj[2];
    const __half* __restrict__ Zb = g_proj[3];
    const __half* __restrict__ Hb = g_proj[4];
    const __half* __restrict__ Sb = g_proj[5];

    size_t rowbase = ((size_t)b * LSZ + (size_t)seg * SEGL) * DSZ + d;

    // forward
    float h = g_carry[(((size_t)b) * NSEG2 + seg) * DSZ + d];
    #pragma unroll 4
    for (int i = 0; i < SEGL; i++) {
        size_t idx = rowbase + (size_t)i * DSZ;
        float z = __half2float(Zf[idx]);
        h = fmaf(1.0f - z, h, z * __half2float(Hf[idx]));
        sv[i * DSZ + d] = h * __half2float(Sf[idx]);
    }
    // backward: these rows reversed form bwd segment 127-seg
    float hb = g_carry[(((size_t)BSZ + b) * NSEG2 + (NSEG2 - 1 - seg)) * DSZ + d];
    #pragma unroll 4
    for (int jj = 0; jj < SEGL; jj++) {
        int i = SEGL - 1 - jj;
        size_t idx = rowbase + (size_t)i * DSZ;
        float z = __half2float(Zb[idx]);
        hb = fmaf(1.0f - z, hb, z * __half2float(Hb[idx]));
        out[idx] = sv[i * DSZ + d] + hb * __half2float(Sb[idx]);
    }
}

// ---------------------------------------------------------------------------
// Launch. Inputs: 0 xs, 1 Wh1, 2 bh1, 3 Wz1, 4 bz1, 5 Ws1, 6 bs1, 7 h01,
//   8 Wh_1, 9 bh_1, 10 Wz_1, 11 bz_1, 12 Ws_1, 13 bs_1, 14 h0_1
// ---------------------------------------------------------------------------
extern "C" void kernel_launch(void* const* d_in, const int* in_sizes, int n_in,
                              void* d_out, int out_size) {
    cudaFuncSetAttribute(gemm_fused,
                         cudaFuncAttributeMaxDynamicSharedMemorySize, GEMM_SMEM);
    cudaFuncSetAttribute(scan_out,
                         cudaFuncAttributeMaxDynamicSharedMemorySize, SEGL * DSZ * 4);

    // widx: 0=z_f(Wz1), 1=h_f(Wh1), 2=s_f(Ws1), 3=z_b(Wz_1), 4=h_b(Wh_1), 5=s_b(Ws_1)
    WPtrs wp;
    wp.W[0] = (const float*)d_in[3];
    wp.W[1] = (const float*)d_in[1];
    wp.W[2] = (const float*)d_in[5];
    wp.W[3] = (const float*)d_in[10];
    wp.W[4] = (const float*)d_in[8];
    wp.W[5] = (const float*)d_in[12];
    BiasPtrs bp;
    bp.b[0] = (const float*)d_in[4];
    bp.b[1] = (const float*)d_in[2];
    bp.b[2] = (const float*)d_in[6];
    bp.b[3] = (const float*)d_in[11];
    bp.b[4] = (const float*)d_in[9];
    bp.b[5] = (const float*)d_in[13];

    prep_w<<<dim3(6, 256), 256>>>(wp);
    gemm_fused<<<dim3(MSZ / 128, 2), 256, GEMM_SMEM>>>(bp, (const float*)d_in[0]);
    scan_pass2<<<dim3(BSZ, 2), DSZ>>>((const float*)d_in[7], (const float*)d_in[14]);
    scan_out<<<dim3(NSEG2, BSZ), DSZ, SEGL * DSZ * 4>>>((float*)d_out);
}

// round 10
// speedup vs baseline: 2.3854x; 1.0281x over previous
#include <cuda_runtime.h>
#include <cuda_fp16.h>
#include <cstdint>
#include <cstddef>

// ---------------------------------------------------------------------------
// BiMiniGRU: B=8, L=8192, C=D=256
//   proj: 6x GEMM [65536,256]x[256,256] + bias (+sigmoid on z,s)
//         fp16 mma.sync (f32 accum), plain PTX (compute_103-legal)
//   One CTA = (64-row M-tile, direction); A resident fp16 in SMEM (32KB).
//   Fused per-direction scan pass1 at 32-step segments.
//   scan: h[t] = (1-z)*h[t-1] + z*h~[t]; out = h_f*s_f + h_b*s_b
// ---------------------------------------------------------------------------

#define BSZ 8
#define LSZ 8192
#define DSZ 256
#define MSZ (BSZ * LSZ)          // 65536
#define MT  64                   // M tile rows
#define SEGL 32                  // scan segment length
#define NSEG2 256                // segments per direction (LSZ/SEGL)

// SMEM: A 4 chunks x 8KB (64 rows x 64 k fp16, SW128) + B 3 stages x 16KB
#define SM_A 0
#define SM_B 32768
#define GEMM_SMEM (32768 + 3 * 16384)    // 81920 -> 2 CTAs/SM

#define SW128(o) ((o) ^ (((o) >> 3) & 0x70))

// ---------------------------------------------------------------------------
// Scratch (__device__ globals; allocation-free rule)
// widx order: 0=z_f, 1=h~_f, 2=s_f, 3=z_b, 4=h~_b, 5=s_b   (fp16 storage)
// ---------------------------------------------------------------------------
__device__ __align__(16) __half g_proj[6][(size_t)MSZ * DSZ];
__device__ __align__(16) __half g_wT[6][DSZ * DSZ];
__device__ float g_segA[2 * BSZ * NSEG2 * DSZ];
__device__ float g_segB[2 * BSZ * NSEG2 * DSZ];
__device__ float g_carry[2 * BSZ * NSEG2 * DSZ];

// ---------------------------------------------------------------------------
// PTX helpers (plain PTX only)
// ---------------------------------------------------------------------------
__device__ __forceinline__ uint32_t smem_u32(const void* p) {
    uint32_t a;
    asm("{ .reg .u64 t; cvta.to.shared.u64 t, %1; cvt.u32.u64 %0, t; }"
        : "=r"(a) : "l"(p));
    return a;
}

#define CP16(dst, src) asm volatile( \
    "cp.async.cg.shared.global [%0], [%1], 16;" :: "r"(dst), "l"(src))
#define CP_COMMIT() asm volatile("cp.async.commit_group;" ::: "memory")
#define CP_WAIT1()  asm volatile("cp.async.wait_group 1;" ::: "memory")

#define LDSM_X4(r, addr) asm volatile( \
    "ldmatrix.sync.aligned.m8n8.x4.shared.b16 {%0,%1,%2,%3}, [%4];" \
    : "=r"((r)[0]), "=r"((r)[1]), "=r"((r)[2]), "=r"((r)[3]) : "r"(addr))
#define LDSM_X2(r, addr) asm volatile( \
    "ldmatrix.sync.aligned.m8n8.x2.shared.b16 {%0,%1}, [%2];" \
    : "=r"((r)[0]), "=r"((r)[1]) : "r"(addr))

#define MMA_F16(cc, a, b) asm volatile( \
    "mma.sync.aligned.m16n8k16.row.col.f32.f16.f16.f32 " \
    "{%0,%1,%2,%3}, {%4,%5,%6,%7}, {%8,%9}, {%0,%1,%2,%3};" \
    : "+f"((cc)[0]), "+f"((cc)[1]), "+f"((cc)[2]), "+f"((cc)[3]) \
    : "r"((a)[0]), "r"((a)[1]), "r"((a)[2]), "r"((a)[3]), \
      "r"((b)[0]), "r"((b)[1]))

// ---------------------------------------------------------------------------
// Precompute: W^T (n-major rows of k) fp16 per weight
// ---------------------------------------------------------------------------
struct WPtrs { const float* W[6]; };
__global__ void prep_w(WPtrs wp) {
    int widx = blockIdx.x;
    int n = blockIdx.y;
    int k = threadIdx.x;
    g_wT[widx][n * DSZ + k] = __float2half_rn(wp.W[widx][(size_t)k * DSZ + n]);
}

// ---------------------------------------------------------------------------
// Fused projection kernel. grid (1024 tiles, 2 dirs), 256 threads
// (8 warps 2m x 4n; warp tile 32x32). A resident; 3 weights x 2 nh x 4 kc.
// Epilogue: bias+activation fp16 stores; then fused pass1 (two 32-parts).
// ---------------------------------------------------------------------------
struct BiasPtrs { const float* b[6]; };

__global__ __launch_bounds__(256, 2)
void gemm_fused(BiasPtrs gb, const float* __restrict__ xs) {
    extern __shared__ __align__(128) char sm[];
    uint32_t sbase = smem_u32(sm);

    const int m0   = blockIdx.x * MT;
    const int dir  = blockIdx.y;
    const int t    = threadIdx.x;
    const int lane = t & 31;
    const int wid  = t >> 5;
    const int wm   = (wid & 1) * 32;
    const int wn   = (wid >> 1) * 32;

    // ---- B chunk loader: q = (wl*2 + nh)*4 + kc, stage = q % 3 ----
    auto loadB = [&](int q) {
        const int wl = q >> 3;
        const int nh = (q >> 2) & 1;
        const int kc = q & 3;
        const __half* __restrict__ Bp = g_wT[dir * 3 + wl];
        uint32_t so = sbase + SM_B + (q % 3) * 16384;
        #pragma unroll
        for (int it = 0; it < 4; it++) {
            int seg = t + it * 256;
            int row = seg >> 3;              // 0..127 (n within half)
            int u   = seg & 7;               // 16B unit in 128B row
            uint32_t sw = SW128((uint32_t)(row * 128 + u * 16));
            CP16(so + sw, Bp + (size_t)(nh * 128 + row) * DSZ + kc * 64 + u * 8);
        }
    };

    loadB(0); CP_COMMIT();
    loadB(1); CP_COMMIT();

    // ---- load + convert the A tile (64 rows x 256 k fp16) ----
    {
        const float4* X4 = reinterpret_cast<const float4*>(xs);
        // 64 rows x 64 float4 = 4096 items; 256 threads x 16 iters
        #pragma unroll
        for (int it = 0; it < 16; it++) {
            int g   = t + it * 256;          // 0..4095
            int row = g >> 6;                // 0..63
            int f4  = g & 63;                // float4 within 256-float row
            float4 v = X4[(size_t)(m0 + row) * 64 + f4];
            __half2 p01 = __floats2half2_rn(v.x, v.y);
            __half2 p23 = __floats2half2_rn(v.z, v.w);
            uint2 u2;
            u2.x = *reinterpret_cast<uint32_t*>(&p01);
            u2.y = *reinterpret_cast<uint32_t*>(&p23);
            int chunk = f4 >> 4;             // k-chunk of 64
            uint32_t sw = SW128((uint32_t)(row * 128 + (f4 & 15) * 8));
            *reinterpret_cast<uint2*>(sm + SM_A + chunk * 8192 + sw) = u2;
        }
    }

    const int gg = lane >> 3, r = lane & 7;

    // ---- main loop: 3 weights x 2 n-halves x 4 k-chunks (24 iters) ----
    int q = 0;
    for (int wl = 0; wl < 3; wl++) {
        const bool do_sig = (wl != 1);       // z, s sigmoid; h~ raw
        const float* __restrict__ bias = gb.b[dir * 3 + wl];
        __half* __restrict__ Out = g_proj[dir * 3 + wl];
        for (int nh = 0; nh < 2; nh++) {
            float c[2][4][4];
            #pragma unroll
            for (int mi = 0; mi < 2; mi++)
                #pragma unroll
                for (int ni = 0; ni < 4; ni++)
                    #pragma unroll
                    for (int p = 0; p < 4; p++) c[mi][ni][p] = 0.0f;

            for (int kc = 0; kc < 4; kc++, q++) {
                CP_WAIT1();                  // group q complete
                __syncthreads();             // visibility + prev compute done
                if (q + 2 < 24) loadB(q + 2);
                CP_COMMIT();

                uint32_t sa = sbase + SM_A + kc * 8192;
                uint32_t sb = sbase + SM_B + (q % 3) * 16384;
                #pragma unroll
                for (int ks = 0; ks < 4; ks++) {
                    uint32_t aoff = SW128((uint32_t)(
                        (wm + (gg & 1) * 8 + r) * 128 + (ks * 16 + (gg >> 1) * 8) * 2));
                    uint32_t boff = SW128((uint32_t)(
                        (wn + r) * 128 + (ks * 16 + (gg & 1) * 8) * 2));
                    uint32_t af[2][4], bf[4][2];
                    #pragma unroll
                    for (int mi = 0; mi < 2; mi++)
                        LDSM_X4(af[mi], sa + aoff + mi * 2048);
                    #pragma unroll
                    for (int ni = 0; ni < 4; ni++)
                        LDSM_X2(bf[ni], sb + boff + ni * 1024);
                    #pragma unroll
                    for (int mi = 0; mi < 2; mi++)
                        #pragma unroll
                        for (int ni = 0; ni < 4; ni++)
                            MMA_F16(c[mi][ni], af[mi], bf[ni]);
                }
            }

            // ---- epilogue for this (wl, nh): bias, act, fp16 store ----
            #pragma unroll
            for (int ni = 0; ni < 4; ni++) {
                const int col = nh * 128 + wn + ni * 8 + (lane & 3) * 2;
                const float2 bb = *reinterpret_cast<const float2*>(bias + col);
                #pragma unroll
                for (int mi = 0; mi < 2; mi++) {
                    const int row = m0 + wm + mi * 16 + (lane >> 2);
                    float v0 = c[mi][ni][0] + bb.x;
                    float v1 = c[mi][ni][1] + bb.y;
                    float v2 = c[mi][ni][2] + bb.x;
                    float v3 = c[mi][ni][3] + bb.y;
                    if (do_sig) {
                        v0 = 1.0f / (1.0f + __expf(-v0));
                        v1 = 1.0f / (1.0f + __expf(-v1));
                        v2 = 1.0f / (1.0f + __expf(-v2));
                        v3 = 1.0f / (1.0f + __expf(-v3));
                    }
                    *reinterpret_cast<__half2*>(Out + (size_t)row * DSZ + col)
                        = __floats2half2_rn(v0, v1);
                    *reinterpret_cast<__half2*>(Out + (size_t)(row + 8) * DSZ + col)
                        = __floats2half2_rn(v2, v3);
                }
            }
        }
    }

    // ---- fused pass1: two 32-step segment affine maps, this dir ----
    __syncthreads();   // all global stores of this CTA visible block-wide
    const int d   = t;
    const int b   = m0 >> 13;                 // batch
    const int s32 = (m0 & (LSZ - 1)) >> 5;    // first 32-seg index
    const __half* __restrict__ Z = g_proj[dir * 3 + 0];
    const __half* __restrict__ H = g_proj[dir * 3 + 1];

    if (dir == 0) {
        #pragma unroll
        for (int part = 0; part < 2; part++) {
            float A = 1.0f, Bc = 0.0f;
            #pragma unroll 4
            for (int i = 0; i < SEGL; i++) {
                size_t idx = (size_t)(m0 + part * SEGL + i) * DSZ + d;
                float z  = __half2float(Z[idx]);
                float ht = __half2float(H[idx]);
                float a = 1.0f - z;
                A = A * a;
                Bc = fmaf(a, Bc, z * ht);
            }
            size_t o = (((size_t)b) * NSEG2 + (s32 + part)) * DSZ + d;
            g_segA[o] = A;  g_segB[o] = Bc;
        }
    } else {
        // bwd: rows of part p, descending -> bwd segment 255 - (s32+p)
        #pragma unroll
        for (int part = 0; part < 2; part++) {
            float A = 1.0f, Bc = 0.0f;
            #pragma unroll 4
            for (int i = 0; i < SEGL; i++) {
                size_t idx = (size_t)(m0 + part * SEGL + (SEGL - 1 - i)) * DSZ + d;
                float z  = __half2float(Z[idx]);
                float ht = __half2float(H[idx]);
                float a = 1.0f - z;
                A = A * a;
                Bc = fmaf(a, Bc, z * ht);
            }
            size_t o = (((size_t)BSZ + b) * NSEG2 + (NSEG2 - 1 - (s32 + part))) * DSZ + d;
            g_segA[o] = A;  g_segB[o] = Bc;
        }
    }
}

// ---------------------------------------------------------------------------
// Scan pass 2: sequential combine over 256 segments; register-batched.
// grid (BSZ, 2), block DSZ
// ---------------------------------------------------------------------------
__global__ void scan_pass2(const float* __restrict__ h0f,
                           const float* __restrict__ h0b) {
    const int d   = threadIdx.x;
    const int b   = blockIdx.x;
    const int dir = blockIdx.y;
    float h = dir ? h0b[d] : h0f[d];
    size_t base = (((size_t)dir * BSZ + b) * NSEG2) * DSZ + d;
    for (int sc = 0; sc < NSEG2 / 16; sc++) {
        float rA[16], rB[16];
        #pragma unroll
        for (int s = 0; s < 16; s++) {
            size_t o = base + (size_t)(sc * 16 + s) * DSZ;
            rA[s] = g_segA[o];
            rB[s] = g_segB[o];
        }
        #pragma unroll
        for (int s = 0; s < 16; s++) {
            size_t o = base + (size_t)(sc * 16 + s) * DSZ;
            g_carry[o] = h;
            h = fmaf(rA[s], h, rB[s]);
        }
    }
}

// ---------------------------------------------------------------------------
// Scan out: both directions fused; fwd staged in 32KB SMEM; half2 channels.
// grid (NSEG2, BSZ), block 128 (each thread owns 2 adjacent d channels)
// ---------------------------------------------------------------------------
__global__ void scan_out(float* __restrict__ out) {
    extern __shared__ float2 sv[];            // [SEGL][128]
    const int d2  = threadIdx.x;              // channel pair: d = 2*d2, 2*d2+1
    const int seg = blockIdx.x;
    const int b   = blockIdx.y;
    const __half2* __restrict__ Zf = reinterpret_cast<const __half2*>(g_proj[0]);
    const __half2* __restrict__ Hf = reinterpret_cast<const __half2*>(g_proj[1]);
    const __half2* __restrict__ Sf = reinterpret_cast<const __half2*>(g_proj[2]);
    const __half2* __restrict__ Zb = reinterpret_cast<const __half2*>(g_proj[3]);
    const __half2* __restrict__ Hb = reinterpret_cast<const __half2*>(g_proj[4]);
    const __half2* __restrict__ Sb = reinterpret_cast<const __half2*>(g_proj[5]);

    // half2-granular row base: row * 128 + d2
    size_t rowbase = ((size_t)b * LSZ + (size_t)seg * SEGL) * 128 + d2;

    // forward
    float2 h = *reinterpret_cast<const float2*>(
        &g_carry[(((size_t)b) * NSEG2 + seg) * DSZ + 2 * d2]);
    #pragma unroll 4
    for (int i = 0; i < SEGL; i++) {
        size_t idx = rowbase + (size_t)i * 128;
        float2 z = __half22float2(Zf[idx]);
        float2 ht = __half22float2(Hf[idx]);
        float2 s = __half22float2(Sf[idx]);
        h.x = fmaf(1.0f - z.x, h.x, z.x * ht.x);
        h.y = fmaf(1.0f - z.y, h.y, z.y * ht.y);
        float2 v; v.x = h.x * s.x; v.y = h.y * s.y;
        sv[i * 128 + d2] = v;
    }
    // backward: these rows reversed form bwd segment NSEG2-1-seg
    float2 hb = *reinterpret_cast<const float2*>(
        &g_carry[(((size_t)BSZ + b) * NSEG2 + (NSEG2 - 1 - seg)) * DSZ + 2 * d2]);
    #pragma unroll 4
    for (int jj = 0; jj < SEGL; jj++) {
        int i = SEGL - 1 - jj;
        size_t idx = rowbase + (size_t)i * 128;
        float2 z = __half22float2(Zb[idx]);
        float2 ht = __half22float2(Hb[idx]);
        float2 s = __half22float2(Sb[idx]);
        hb.x = fmaf(1.0f - z.x, hb.x, z.x * ht.x);
        hb.y = fmaf(1.0f - z.y, hb.y, z.y * ht.y);
        float2 v = sv[i * 128 + d2];
        v.x = fmaf(hb.x, s.x, v.x);
        v.y = fmaf(hb.y, s.y, v.y);
        *reinterpret_cast<float2*>(&out[idx * 2]) = v;
    }
}

// ---------------------------------------------------------------------------
// Launch. Inputs: 0 xs, 1 Wh1, 2 bh1, 3 Wz1, 4 bz1, 5 Ws1, 6 bs1, 7 h01,
//   8 Wh_1, 9 bh_1, 10 Wz_1, 11 bz_1, 12 Ws_1, 13 bs_1, 14 h0_1
// ---------------------------------------------------------------------------
extern "C" void kernel_launch(void* const* d_in, const int* in_sizes, int n_in,
                              void* d_out, int out_size) {
    cudaFuncSetAttribute(gemm_fused,
                         cudaFuncAttributeMaxDynamicSharedMemorySize, GEMM_SMEM);

    // widx: 0=z_f(Wz1), 1=h_f(Wh1), 2=s_f(Ws1), 3=z_b(Wz_1), 4=h_b(Wh_1), 5=s_b(Ws_1)
    WPtrs wp;
    wp.W[0] = (const float*)d_in[3];
    wp.W[1] = (const float*)d_in[1];
    wp.W[2] = (const float*)d_in[5];
    wp.W[3] = (const float*)d_in[10];
    wp.W[4] = (const float*)d_in[8];
    wp.W[5] = (const float*)d_in[12];
    BiasPtrs bp;
    bp.b[0] = (const float*)d_in[4];
    bp.b[1] = (const float*)d_in[2];
    bp.b[2] = (const float*)d_in[6];
    bp.b[3] = (const float*)d_in[11];
    bp.b[4] = (const float*)d_in[9];
    bp.b[5] = (const float*)d_in[13];

    prep_w<<<dim3(6, 256), 256>>>(wp);
    gemm_fused<<<dim3(MSZ / MT, 2), 256, GEMM_SMEM>>>(bp, (const float*)d_in[0]);
    scan_pass2<<<dim3(BSZ, 2), DSZ>>>((const float*)d_in[7], (const float*)d_in[14]);
    scan_out<<<dim3(NSEG2, BSZ), 128, SEGL * 128 * sizeof(float2)>>>((float*)d_out);
}